// round 10
// baseline (speedup 1.0000x reference)
#include <cuda_runtime.h>
#include <cuda_bf16.h>
#include <stdint.h>

#define CH 64
#define HH 224
#define WW 224
#define HW (HH*WW)

#define TPX 32            // output tile width
#define TRY 8             // output tile rows
#define IW  34            // staged input width (x0-1 .. x0+32)
#define IR  10            // staged input rows  (y0-1 .. y0+8)

// Interleaved plane: row = (r*IW+q) pixel, 256 B = K128 bf16:
//   k = 4*cp + {ci0 hi, ci0 lo, ci1 hi, ci1 lo},  ci pair = (2cp, 2cp+1)
#define P_BYTES (IR*IW*256)        // 87040
#define WOFF    ((uint32_t)P_BYTES)
#define WSLICE  24576u             // per-kw weight slice: [kh 0..2][c 0..7][wn 0..1][lane] uint4
#define SMEM_DYN (P_BYTES + WSLICE)   // 111616 -> 2 CTAs/SM

// Compact duplicable B fragments: [kw][kh][c][wn][lane] uint4,
// component g: bf16x2( sign w[n][8c+(lane&3)], sign w[n][8c+4+(lane&3)] ), n = wn*32+g*8+lane/4
__device__ uint4 g_wc[3 * 3 * 8 * 2 * 32];   // 73728 B

__global__ void prep_wc(const float* __restrict__ w) {
    int idx = blockIdx.x * blockDim.x + threadIdx.x;
    if (idx >= 3 * 3 * 8 * 2 * 32) return;
    int lane = idx & 31;
    int wn   = (idx >> 5) & 1;
    int c    = (idx >> 6) & 7;
    int t3   = idx >> 9;            // 0..8
    int kh   = t3 % 3, kw = t3 / 3;
    int tap  = kh * 3 + kw;
    uint32_t rr[4];
#pragma unroll
    for (int g = 0; g < 4; g++) {
        int n   = wn * 32 + g * 8 + (lane >> 2);
        int ci0 = 8 * c + (lane & 3);
        float v0 = w[(n * 64 + ci0)     * 9 + tap];
        float v1 = w[(n * 64 + ci0 + 4) * 9 + tap];
        float s0 = (v0 > 0.f) ? 1.f : ((v0 < 0.f) ? -1.f : 0.f);
        float s1 = (v1 > 0.f) ? 1.f : ((v1 < 0.f) ? -1.f : 0.f);
        __nv_bfloat16 h0 = __float2bfloat16(s0), h1 = __float2bfloat16(s1);
        rr[g] = (uint32_t)__bfloat16_as_ushort(h0) | ((uint32_t)__bfloat16_as_ushort(h1) << 16);
    }
    g_wc[idx] = make_uint4(rr[0], rr[1], rr[2], rr[3]);
}

__device__ __forceinline__ uint32_t smem_u32(const void* p) {
    uint32_t a;
    asm("{ .reg .u64 t; cvta.to.shared.u64 t, %1; cvt.u32.u64 %0, t; }" : "=r"(a) : "l"(p));
    return a;
}
// swizzle for 256B rows: XOR 16B-slot bits [4:6] with px&7 (off bits [8:10])
__device__ __forceinline__ uint32_t swz2(uint32_t off) {
    return off ^ ((off >> 4) & 0x70);
}
__device__ __forceinline__ void sts64(uint32_t a, uint32_t v0, uint32_t v1) {
    asm volatile("st.shared.v2.b32 [%0], {%1,%2};" :: "r"(a), "r"(v0), "r"(v1));
}
__device__ __forceinline__ void sts128(uint32_t a, uint4 v) {
    asm volatile("st.shared.v4.b32 [%0], {%1,%2,%3,%4};"
                 :: "r"(a), "r"(v.x), "r"(v.y), "r"(v.z), "r"(v.w));
}
__device__ __forceinline__ uint4 lds128(uint32_t a) {
    uint4 v;
    asm volatile("ld.shared.v4.b32 {%0,%1,%2,%3}, [%4];"
                 : "=r"(v.x), "=r"(v.y), "=r"(v.z), "=r"(v.w) : "r"(a));
    return v;
}
__device__ __forceinline__ void ldm_x4(uint32_t& r0, uint32_t& r1, uint32_t& r2, uint32_t& r3,
                                       uint32_t addr) {
    asm volatile("ldmatrix.sync.aligned.m8n8.x4.shared.b16 {%0,%1,%2,%3}, [%4];"
                 : "=r"(r0), "=r"(r1), "=r"(r2), "=r"(r3) : "r"(addr));
}
__device__ __forceinline__ void mma16816(float* d, uint32_t a0, uint32_t a1, uint32_t a2,
                                         uint32_t a3, uint32_t b0, uint32_t b1) {
    asm volatile("mma.sync.aligned.m16n8k16.row.col.f32.bf16.bf16.f32 "
                 "{%0,%1,%2,%3},{%4,%5,%6,%7},{%8,%9},{%0,%1,%2,%3};"
                 : "+f"(d[0]), "+f"(d[1]), "+f"(d[2]), "+f"(d[3])
                 : "r"(a0), "r"(a1), "r"(a2), "r"(a3), "r"(b0), "r"(b1));
}

__global__ void __launch_bounds__(256, 2)
bconv_mma(const float* __restrict__ x, const float* __restrict__ bias,
          float* __restrict__ out)
{
    extern __shared__ char smraw[];
    const uint32_t smb = smem_u32(smraw);
    const int tid = threadIdx.x, lane = tid & 31, wid = tid >> 5;
    const int n = blockIdx.z, x0 = blockIdx.x * TPX, y0 = blockIdx.y * TRY;

    // ---- stage interleaved hi/lo plane: (10 r x 34 q) x 32 cp, one sts64 each ----
    const float* xn = x + (size_t)n * CH * HW;
    for (int idx = tid; idx < IR * IW * 32; idx += 256) {
        int q  = idx % IW;
        int rc = idx / IW;
        int r  = rc % IR;
        int cp = rc / IR;                 // ci pair 0..31
        int gx = x0 - 1 + q, ry = y0 - 1 + r;
        float v0 = 0.f, v1 = 0.f;
        if (gx >= 0 && gx < WW && ry >= 0 && ry < HH) {
            const float* p = xn + (size_t)(cp * 2) * HW + (size_t)ry * WW + gx;
            v0 = __ldg(p);
            v1 = __ldg(p + HW);
        }
        __nv_bfloat16 h0 = __float2bfloat16(v0), h1 = __float2bfloat16(v1);
        __nv_bfloat16 l0 = __float2bfloat16(v0 - __bfloat162float(h0));
        __nv_bfloat16 l1 = __float2bfloat16(v1 - __bfloat162float(h1));
        uint32_t w0 = (uint32_t)__bfloat16_as_ushort(h0) | ((uint32_t)__bfloat16_as_ushort(l0) << 16);
        uint32_t w1 = (uint32_t)__bfloat16_as_ushort(h1) | ((uint32_t)__bfloat16_as_ushort(l1) << 16);
        sts64(smb + swz2((uint32_t)(r * IW + q) * 256u + (uint32_t)cp * 8u), w0, w1);
    }

    // ---- warp tiling: warp wm covers output rows {2wm, 2wm+1} x 32 px; wn = co half ----
    const int wn = wid & 1;
    const int wm = wid >> 1;

    float acc[4][4][4];                    // [f=dy*2+xh][g][reg]
#pragma unroll
    for (int f = 0; f < 4; f++)
#pragma unroll
        for (int g = 0; g < 4; g++)
#pragma unroll
            for (int r = 0; r < 4; r++) acc[f][g][r] = 0.f;

    const uint32_t wb_lane = smb + WOFF + (uint32_t)wn * 512u + (uint32_t)lane * 16u;
    const uint32_t rowc = (uint32_t)(2 * wm) * 34u + (uint32_t)(lane & 15);
    const uint32_t kbc  = ((uint32_t)lane >> 4) * 16u;

#pragma unroll
    for (int kw = 0; kw < 3; kw++) {
        __syncthreads();                   // prior reads of weight buffer done
        {
            const uint4* wp = g_wc + (size_t)kw * 1536;
            for (int i = tid; i < 1536; i += 256)
                sts128(smb + WOFF + (uint32_t)i * 16u, __ldg(wp + i));
        }
        __syncthreads();                   // weights + (kw=0: plane) staged

#pragma unroll
        for (int c = 0; c < 8; c++) {
            // compact B for 3 kh -> duplicated b-regs via PRMT
            uint32_t b0a[3][4], b1a[3][4];
#pragma unroll
            for (int kh = 0; kh < 3; kh++) {
                uint4 W = lds128(wb_lane + (uint32_t)((kh * 8 + c) * 2) * 512u);
                uint32_t wgs[4] = {W.x, W.y, W.z, W.w};
#pragma unroll
                for (int g = 0; g < 4; g++) {
                    b0a[kh][g] = __byte_perm(wgs[g], wgs[g], 0x1010);   // dup low bf16 (r2=0)
                    b1a[kh][g] = __byte_perm(wgs[g], wgs[g], 0x3232);   // dup high bf16 (r2=1)
                }
            }
#pragma unroll
            for (int ri = 0; ri < 4; ri++) {
#pragma unroll
                for (int xh = 0; xh < 2; xh++) {
                    uint32_t off = (rowc + (uint32_t)(ri * 34 + xh * 16 + kw)) * 256u
                                 + (uint32_t)c * 32u + kbc;
                    uint32_t a0, a1, a2, a3;
                    ldm_x4(a0, a1, a2, a3, smb + swz2(off));
                    // valid (dy, kh): kh = ri - dy
#pragma unroll
                    for (int dy = 0; dy < 2; dy++) {
                        int kh = ri - dy;
                        if (kh < 0 || kh > 2) continue;
                        const int f = dy * 2 + xh;
#pragma unroll
                        for (int g = 0; g < 4; g++)
                            mma16816(acc[f][g], a0, a1, a2, a3, b0a[kh][g], b1a[kh][g]);
                    }
                }
            }
        }
    }

    // ---- epilogue: bias + store ----
    const int r0 = lane >> 2, c0 = (lane & 3) * 2;
    float bl[4], bh[4];
#pragma unroll
    for (int g = 0; g < 4; g++) {
        int co = wn * 32 + g * 8 + c0;
        bl[g] = __ldg(bias + co);
        bh[g] = __ldg(bias + co + 1);
    }
#pragma unroll
    for (int f = 0; f < 4; f++) {
        int y  = y0 + 2 * wm + (f >> 1);
        int xb = x0 + (f & 1) * 16;
#pragma unroll
        for (int g = 0; g < 4; g++) {
            int co = wn * 32 + g * 8 + c0;
            float* o0 = out + (((size_t)n * CH + co)     * HH + y) * WW + xb;
            float* o1 = out + (((size_t)n * CH + co + 1) * HH + y) * WW + xb;
            o0[r0]     = acc[f][g][0] + bl[g];
            o1[r0]     = acc[f][g][1] + bh[g];
            o0[r0 + 8] = acc[f][g][2] + bl[g];
            o1[r0 + 8] = acc[f][g][3] + bh[g];
        }
    }
}

extern "C" void kernel_launch(void* const* d_in, const int* in_sizes, int n_in,
                              void* d_out, int out_size) {
    const float* x    = (const float*)d_in[0];   // [32,64,224,224]
    const float* w    = (const float*)d_in[1];   // [64,64,3,3]
    const float* bias = (const float*)d_in[2];   // [64]
    float* out = (float*)d_out;

    prep_wc<<<(3 * 3 * 8 * 2 * 32 + 255) / 256, 256>>>(w);

    cudaFuncSetAttribute(bconv_mma, cudaFuncAttributeMaxDynamicSharedMemorySize, SMEM_DYN);
    dim3 grid(WW / TPX, HH / TRY, 32);   // (7, 28, 32) = 6272 CTAs
    bconv_mma<<<grid, 256, SMEM_DYN>>>(x, bias, out);
}

// round 11
// speedup vs baseline: 1.6509x; 1.6509x over previous
#include <cuda_runtime.h>
#include <cuda_fp16.h>
#include <stdint.h>

#define CH 64
#define HH 224
#define WW 224
#define HW (HH*WW)

#define TPX 32          // output tile width
#define TRY 8           // output tile rows
#define IW  34          // staged input width  (x0-1 .. x0+32)
#define IR  10          // staged input rows   (y0-1 .. y0+8)

#define P_BYTES (IR*IW*128)                 // 43520: fp16 plane [(r,q)][ci 0..63]
#define OFF_WB  ((uint32_t)P_BYTES)         // weight tap ring: 2 x 8192 B
#define SMEM_DYN (P_BYTES + 2*8192)         // 59904 B -> 2 CTAs/SM

// B fragments pre-packed in mma.m16n8k16.f16 fragment order:
// [t][c][wn][half][lane] ; half0 = {g0,g1}, half1 = {g2,g3}
// lane holds {B[k][n], B[k+1][n]} with n = wn*32+g*8+lane/4, k = 16c+(lane%4)*2+r2*8
__device__ uint4 g_wf[9 * 4 * 2 * 2 * 32];   // 73728 B (L2-resident)

__global__ void prep_wfrag(const float* __restrict__ w) {
    int idx = blockIdx.x * blockDim.x + threadIdx.x;
    if (idx >= 9 * 4 * 2 * 2 * 32) return;
    int lane = idx & 31;
    int half = (idx >> 5) & 1;
    int wn   = (idx >> 6) & 1;
    int c    = (idx >> 7) & 3;
    int t    = idx >> 9;
    uint32_t r[4];
#pragma unroll
    for (int j = 0; j < 4; j++) {
        int g  = half * 2 + (j >> 1);
        int r2 = j & 1;
        int n  = wn * 32 + g * 8 + (lane >> 2);
        int k  = c * 16 + (lane & 3) * 2 + r2 * 8;      // k = ci, 0..62
        float v0 = w[(n * 64 + k)     * 9 + t];
        float v1 = w[(n * 64 + k + 1) * 9 + t];
        float s0 = (v0 > 0.f) ? 1.f : ((v0 < 0.f) ? -1.f : 0.f);
        float s1 = (v1 > 0.f) ? 1.f : ((v1 < 0.f) ? -1.f : 0.f);
        __half h0 = __float2half(s0), h1 = __float2half(s1);
        r[j] = (uint32_t)__half_as_ushort(h0) | ((uint32_t)__half_as_ushort(h1) << 16);
    }
    g_wf[idx] = make_uint4(r[0], r[1], r[2], r[3]);
}

__device__ __forceinline__ uint32_t smem_u32(const void* p) {
    uint32_t a;
    asm("{ .reg .u64 t; cvta.to.shared.u64 t, %1; cvt.u32.u64 %0, t; }" : "=r"(a) : "l"(p));
    return a;
}
__device__ __forceinline__ uint32_t swz(uint32_t off) {   // SW128-atom XOR swizzle
    return off ^ ((off >> 3) & 0x70);
}
__device__ __forceinline__ void sts32(uint32_t a, uint32_t v) {
    asm volatile("st.shared.b32 [%0], %1;" :: "r"(a), "r"(v));
}
__device__ __forceinline__ void sts128(uint32_t a, uint4 v) {
    asm volatile("st.shared.v4.b32 [%0], {%1,%2,%3,%4};"
                 :: "r"(a), "r"(v.x), "r"(v.y), "r"(v.z), "r"(v.w));
}
__device__ __forceinline__ uint4 lds128(uint32_t a) {
    uint4 v;
    asm volatile("ld.shared.v4.b32 {%0,%1,%2,%3}, [%4];"
                 : "=r"(v.x), "=r"(v.y), "=r"(v.z), "=r"(v.w) : "r"(a));
    return v;
}
__device__ __forceinline__ void ldm_x4(uint32_t& r0, uint32_t& r1, uint32_t& r2, uint32_t& r3,
                                       uint32_t addr) {
    asm volatile("ldmatrix.sync.aligned.m8n8.x4.shared.b16 {%0,%1,%2,%3}, [%4];"
                 : "=r"(r0), "=r"(r1), "=r"(r2), "=r"(r3) : "r"(addr));
}
__device__ __forceinline__ void mma16816(float* d, uint32_t a0, uint32_t a1, uint32_t a2,
                                         uint32_t a3, uint32_t b0, uint32_t b1) {
    asm volatile("mma.sync.aligned.m16n8k16.row.col.f32.f16.f16.f32 "
                 "{%0,%1,%2,%3},{%4,%5,%6,%7},{%8,%9},{%0,%1,%2,%3};"
                 : "+f"(d[0]), "+f"(d[1]), "+f"(d[2]), "+f"(d[3])
                 : "r"(a0), "r"(a1), "r"(a2), "r"(a3), "r"(b0), "r"(b1));
}

__global__ void __launch_bounds__(256, 2)
bconv_mma(const float* __restrict__ x, const float* __restrict__ bias,
          float* __restrict__ out)
{
    extern __shared__ char smraw[];
    const uint32_t smb = smem_u32(smraw);
    const int tid = threadIdx.x, lane = tid & 31, wid = tid >> 5;
    const int n = blockIdx.z, x0 = blockIdx.x * TPX, y0 = blockIdx.y * TRY;

    // ---- stage fp16 input plane: (10 rows x 34 px) x 32 ci-pairs, one sts32 each ----
    const float* xn = x + (size_t)n * CH * HW;
    for (int idx = tid; idx < IR * IW * 32; idx += 256) {
        int q  = idx % IW;
        int rc = idx / IW;
        int r  = rc % IR;
        int cp = rc / IR;                 // ci pair 0..31
        int gx = x0 - 1 + q, ry = y0 - 1 + r;
        float v0 = 0.f, v1 = 0.f;
        if (gx >= 0 && gx < WW && ry >= 0 && ry < HH) {
            const float* p = xn + (size_t)(cp * 2) * HW + (size_t)ry * WW + gx;
            v0 = __ldg(p);
            v1 = __ldg(p + HW);
        }
        __half h0 = __float2half(v0), h1 = __float2half(v1);
        uint32_t hp = (uint32_t)__half_as_ushort(h0) | ((uint32_t)__half_as_ushort(h1) << 16);
        sts32(smb + swz((uint32_t)(r * IW + q) * 128u + (uint32_t)cp * 4u), hp);
    }

    // ---- prime weight tap ring: tap 0 -> buf 0 (512 uint4, coalesced) ----
    {
        const uint4* wp = g_wf;                    // tap 0 block
#pragma unroll
        for (int i = tid; i < 512; i += 256)
            sts128(smb + OFF_WB + (uint32_t)i * 16u, __ldg(wp + i));
    }
    __syncthreads();

    // ---- warp tiling: 4(M) x 2(N); warp tile M64 x N32 ----
    const int wn = wid & 1;          // co half
    const int wm = wid >> 1;         // pixel quarter

    uint32_t arowb[4];
#pragma unroll
    for (int f = 0; f < 4; f++) {
        int cc = wm * 4 + f;
        int yf = cc >> 1;
        int xxf = (cc & 1) * 16 + (lane & 15);
        arowb[f] = (uint32_t)(yf * IW + xxf) * 128u;
    }
    const uint32_t acol = ((uint32_t)lane >> 4) * 16u;    // k-halves for A
    const uint32_t bln = (uint32_t)lane * 16u;

    float acc[4][4][4];
#pragma unroll
    for (int f = 0; f < 4; f++)
#pragma unroll
        for (int g = 0; g < 4; g++)
#pragma unroll
            for (int r = 0; r < 4; r++) acc[f][g][r] = 0.f;

#pragma unroll
    for (int t = 0; t < 9; t++) {
        // prefetch next tap's fragments into the other ring slot
        if (t + 1 < 9) {
            const uint4* wp = g_wf + (size_t)(t + 1) * 512;
            uint32_t dst = smb + OFF_WB + (uint32_t)((t + 1) & 1) * 8192u;
#pragma unroll
            for (int i = tid; i < 512; i += 256)
                sts128(dst + (uint32_t)i * 16u, __ldg(wp + i));
        }

        const int kh = t / 3, kw = t % 3;
        const uint32_t shiftA = (uint32_t)(kh * IW + kw) * 128u;
        const uint32_t wbuf = smb + OFF_WB + (uint32_t)(t & 1) * 8192u + (uint32_t)wn * 1024u + bln;
#pragma unroll
        for (int c = 0; c < 4; c++) {
            // B fragments: 2 conflict-free lds.128 in mma fragment order
            uint4 B0 = lds128(wbuf + (uint32_t)c * 2048u);          // half 0: g0,g1
            uint4 B1 = lds128(wbuf + (uint32_t)c * 2048u + 512u);   // half 1: g2,g3
            const uint32_t kofs = shiftA + (uint32_t)c * 32u + acol;
#pragma unroll
            for (int f = 0; f < 4; f++) {
                uint32_t a0, a1, a2, a3;
                ldm_x4(a0, a1, a2, a3, smb + swz(arowb[f] + kofs));
                mma16816(acc[f][0], a0, a1, a2, a3, B0.x, B0.y);
                mma16816(acc[f][1], a0, a1, a2, a3, B0.z, B0.w);
                mma16816(acc[f][2], a0, a1, a2, a3, B1.x, B1.y);
                mma16816(acc[f][3], a0, a1, a2, a3, B1.z, B1.w);
            }
        }
        __syncthreads();   // ring-slot rotation barrier (copy t+1 visible; slot t free)
    }

    // ---- epilogue: bias + store ----
    const int r0 = lane >> 2, c0 = (lane & 3) * 2;
    float bl[4], bh[4];
#pragma unroll
    for (int g = 0; g < 4; g++) {
        int co = wn * 32 + g * 8 + c0;
        bl[g] = __ldg(bias + co);
        bh[g] = __ldg(bias + co + 1);
    }
#pragma unroll
    for (int f = 0; f < 4; f++) {
        int cc = wm * 4 + f;
        int y = y0 + (cc >> 1);
        int xb = x0 + (cc & 1) * 16;
#pragma unroll
        for (int g = 0; g < 4; g++) {
            int co = wn * 32 + g * 8 + c0;
            float* o0 = out + (((size_t)n * CH + co)     * HH + y) * WW + xb;
            float* o1 = out + (((size_t)n * CH + co + 1) * HH + y) * WW + xb;
            o0[r0]     = acc[f][g][0] + bl[g];
            o1[r0]     = acc[f][g][1] + bh[g];
            o0[r0 + 8] = acc[f][g][2] + bl[g];
            o1[r0 + 8] = acc[f][g][3] + bh[g];
        }
    }
}

extern "C" void kernel_launch(void* const* d_in, const int* in_sizes, int n_in,
                              void* d_out, int out_size) {
    const float* x    = (const float*)d_in[0];   // [32,64,224,224]
    const float* w    = (const float*)d_in[1];   // [64,64,3,3]
    const float* bias = (const float*)d_in[2];   // [64]
    float* out = (float*)d_out;

    prep_wfrag<<<(9 * 4 * 2 * 2 * 32 + 255) / 256, 256>>>(w);

    cudaFuncSetAttribute(bconv_mma, cudaFuncAttributeMaxDynamicSharedMemorySize, SMEM_DYN);
    dim3 grid(WW / TPX, HH / TRY, 32);   // (7, 28, 32) = 6272 CTAs
    bconv_mma<<<grid, 256, SMEM_DYN>>>(x, bias, out);
}